// round 11
// baseline (speedup 1.0000x reference)
#include <cuda_runtime.h>
#include <cstdint>

#define DD 768
#define HH 64
#define EE 20
#define TILE_M 128
#define KC 32
#define NCHUNK (DD / KC)
#define SA 36                      // A smem stride (floats), conflict-free frags
#define A_FLOATS (TILE_M * SA)     // 4608 per buffer

// Precomputed fold products (device globals: no allocation allowed)
__device__ float g_Wc[DD * HH];     // W1_mem + ment (.) W1_hadamard   [768 x 64]
__device__ float g_bias[HH];        // b1 + ment @ W1_mention          [64]
__device__ float g_dist[10 * HH];   // dist_table @ W1_dist            [10 x 64]
__device__ float g_cnt[10 * HH];    // counter_table @ W1_cnt          [10 x 64]

__global__ __launch_bounds__(256) void precompute_all(
    const float* __restrict__ ment, const float* __restrict__ W1,
    const float* __restrict__ b1, const float* __restrict__ dist_t,
    const float* __restrict__ cnt_t) {
    const int t = threadIdx.x;
    const int blk = blockIdx.x;
    if (blk < 192) {
        int idx = blk * 256 + t;
        int d = idx >> 6;
        g_Wc[idx] = W1[idx] + ment[d] * W1[(2 * DD) * HH + idx];
    } else if (blk < 256) {
        const int h = blk - 192;
        float s = 0.f;
#pragma unroll
        for (int j = 0; j < 3; j++) {
            int d = t + 256 * j;
            s += ment[d] * W1[(DD + d) * HH + h];
        }
#pragma unroll
        for (int o = 16; o > 0; o >>= 1) s += __shfl_xor_sync(0xffffffffu, s, o);
        __shared__ float red[8];
        if ((t & 31) == 0) red[t >> 5] = s;
        __syncthreads();
        if (t == 0) {
            float tot = b1[h];
#pragma unroll
            for (int w = 0; w < 8; w++) tot += red[w];
            g_bias[h] = tot;
        }
    } else {
        const int b = blk - 256;
        if (t < 128) {
            const int h = t & 63;
            const float* tab = (t < 64) ? dist_t : cnt_t;
            const int wo = (t < 64) ? (3 * DD) : (3 * DD + EE);
            float s = 0.f;
#pragma unroll
            for (int e = 0; e < EE; e++)
                s += tab[b * EE + e] * W1[(wo + e) * HH + h];
            if (t < 64) g_dist[b * HH + h] = s;
            else        g_cnt[b * HH + h] = s;
        }
    }
}

// Exact integer bucket: identity for c<=4, floor(log2(c))+3 above, clamp [0,9]
__device__ __forceinline__ int get_bucket(int c) {
    int b = (c <= 4) ? c : (34 - __clz(c));
    b = b > 9 ? 9 : b;
    return b < 0 ? 0 : b;
}

// Raw fp32 bits as tf32 operand (HW truncates mantissa; rel_err margin is huge)
__device__ __forceinline__ uint32_t fbits(float f) { return __float_as_uint(f); }

__device__ __forceinline__ void mma_tf32(float* d, const uint32_t* a, uint32_t b0, uint32_t b1) {
    asm volatile(
        "mma.sync.aligned.m16n8k8.row.col.f32.tf32.tf32.f32 "
        "{%0,%1,%2,%3},{%4,%5,%6,%7},{%8,%9},{%0,%1,%2,%3};"
        : "+f"(d[0]), "+f"(d[1]), "+f"(d[2]), "+f"(d[3])
        : "r"(a[0]), "r"(a[1]), "r"(a[2]), "r"(a[3]), "r"(b0), "r"(b1));
}

__device__ __forceinline__ void cpa16(uint32_t saddr, const void* gaddr) {
    asm volatile("cp.async.cg.shared.global [%0], [%1], 16;" :: "r"(saddr), "l"(gaddr));
}
__device__ __forceinline__ void cpa_commit() { asm volatile("cp.async.commit_group;"); }
template <int N> __device__ __forceinline__ void cpa_wait() {
    asm volatile("cp.async.wait_group %0;" :: "n"(N));
}

__global__ __launch_bounds__(128, 4) void main_kernel(
    const float* __restrict__ memv, const int* __restrict__ entc,
    const int* __restrict__ lastm, const int* __restrict__ mstart,
    const float* __restrict__ W2, const float* __restrict__ b2,
    float* __restrict__ out, int M) {
    __shared__ float As[2 * A_FLOATS];         // [2][128][SA]
    __shared__ float s_bias[HH], s_w2[HH], s_dist[10 * HH], s_cnt[10 * HH];

    const int t = threadIdx.x;
    const int w = t >> 5, lane = t & 31;
    const int g = lane >> 2, c = lane & 3;
    const int R0 = blockIdx.x * TILE_M;

    if (t < 64) { s_bias[t] = g_bias[t]; s_w2[t] = W2[t]; }
    for (int i = t; i < 640; i += 128) { s_dist[i] = g_dist[i]; s_cnt[i] = g_cnt[i]; }

    const uint32_t sA = (uint32_t)__cvta_generic_to_shared(As);

    // --- async A chunk copy: global -> smem buffer b (one row per thread) ---
    auto copy_chunk = [&](int b, int kc) {
        const int d0 = kc * KC;
        int row = t;
        if (R0 + row < M) {
            uint32_t dst = sA + (b * A_FLOATS + row * SA) * 4;
            const float* src = memv + (size_t)(R0 + row) * DD + d0;
#pragma unroll
            for (int j = 0; j < 8; j++) cpa16(dst + 16 * j, src + 4 * j);
        }
    };

    float acc[2][8][4];
#pragma unroll
    for (int mt = 0; mt < 2; mt++)
#pragma unroll
        for (int nt = 0; nt < 8; nt++)
#pragma unroll
            for (int i = 0; i < 4; i++) acc[mt][nt][i] = 0.f;

    const int r0 = w * 32;

    copy_chunk(0, 0);
    cpa_commit();

    int buf = 0;
    for (int kc = 0; kc < NCHUNK; kc++) {
        if (kc + 1 < NCHUNK) {
            copy_chunk(buf ^ 1, kc + 1);
            cpa_commit();
            cpa_wait<1>();
        } else {
            cpa_wait<0>();
        }
        __syncthreads();

        const float* A = As + buf * A_FLOATS;
        const int d0 = kc * KC;
#pragma unroll
        for (int kt = 0; kt < 4; kt++) {
            const int k0 = kt * 8;
            uint32_t a[2][4];
#pragma unroll
            for (int mt = 0; mt < 2; mt++) {
                const float* ap = A + (r0 + 16 * mt + g) * SA + k0 + c;
                a[mt][0] = fbits(ap[0]);
                a[mt][1] = fbits(ap[8 * SA]);
                a[mt][2] = fbits(ap[4]);
                a[mt][3] = fbits(ap[8 * SA + 4]);
            }
            // B fragments straight from L2/L1 (g_Wc broadcast across warps)
            const float* bbase = g_Wc + (size_t)(d0 + k0 + c) * HH + g;
#pragma unroll
            for (int nt = 0; nt < 8; nt++) {
                uint32_t b0 = fbits(bbase[nt * 8]);
                uint32_t b1 = fbits(bbase[4 * HH + nt * 8]);
                mma_tf32(acc[0][nt], a[0], b0, b1);
                mma_tf32(acc[1][nt], a[1], b0, b1);
            }
        }
        __syncthreads();
        buf ^= 1;
    }

    // Epilogue: bias + feature lookups + ReLU + dot W2; quad-reduce per row
    const int ms0 = mstart[0];
    const float b2v = b2[0];
#pragma unroll
    for (int mt = 0; mt < 2; mt++) {
#pragma unroll
        for (int half = 0; half < 2; half++) {
            int r = r0 + 16 * mt + 8 * half + g;
            int gm = R0 + r;
            int gmc = (gm < M) ? gm : 0;
            int cnt_v = entc[gmc];
            int bd = get_bucket(ms0 - lastm[gmc]);
            int bc = get_bucket(cnt_v);
            const float* dh = &s_dist[bd * HH];
            const float* ch = &s_cnt[bc * HH];
            float s = 0.f;
#pragma unroll
            for (int nt = 0; nt < 8; nt++) {
                int col = 8 * nt + 2 * c;
                float v0 = acc[mt][nt][2 * half + 0];
                float v1 = acc[mt][nt][2 * half + 1];
                float e0 = v0 + s_bias[col] + dh[col] + ch[col];
                float e1 = v1 + s_bias[col + 1] + dh[col + 1] + ch[col + 1];
                s = fmaf(fmaxf(e0, 0.f), s_w2[col], s);
                s = fmaf(fmaxf(e1, 0.f), s_w2[col + 1], s);
            }
            s += __shfl_xor_sync(0xffffffffu, s, 1);
            s += __shfl_xor_sync(0xffffffffu, s, 2);
            if (c == 0 && gm < M)
                out[gm] = (cnt_v > 0) ? (s + b2v) : -10000.0f;
        }
    }
    if (blockIdx.x == 0 && t == 0) out[M] = 0.0f;
}

extern "C" void kernel_launch(void* const* d_in, const int* in_sizes, int n_in,
                              void* d_out, int out_size) {
    const float* ment   = (const float*)d_in[0];
    const float* memv   = (const float*)d_in[1];
    const float* dist_t = (const float*)d_in[2];
    const float* cnt_t  = (const float*)d_in[3];
    const float* W1     = (const float*)d_in[4];
    const float* b1     = (const float*)d_in[5];
    const float* W2     = (const float*)d_in[6];
    const float* b2     = (const float*)d_in[7];
    const int*   entc   = (const int*)d_in[8];
    const int*   lastm  = (const int*)d_in[9];
    const int*   ms     = (const int*)d_in[10];
    int M = in_sizes[8];

    precompute_all<<<266, 256>>>(ment, W1, b1, dist_t, cnt_t);
    main_kernel<<<(M + TILE_M - 1) / TILE_M, 128>>>(
        memv, entc, lastm, ms, W2, b2, (float*)d_out, M);
}